// round 16
// baseline (speedup 1.0000x reference)
#include <cuda_runtime.h>

#define B_DIM 16
#define G_DIM 1708
#define GV4   (G_DIM / 4)        // 427 active float4 groups in phase A
#define H_DIM 5
#define NC 16                    // Taylor n = 0..15; 4.5^16/16!/e^4.5 ~ 1.5e-5 at guard
#define GUARD 4.5f
#define NTHREADS 448
#define NWARPS 14
#define CHUNK ((G_DIM + H_DIM - 1) / H_DIM)   // 342 rows per CTA in phase B

// Per-(b,h) coefficients [S0..15, M0..15] (already /n!) + kam; tiny L2 exchange.
__device__ float    g_coef[B_DIM * H_DIM * 32];
__device__ float    g_kam[B_DIM * H_DIM];
__device__ unsigned g_cnt[B_DIM];   // monotone publish counter (replay-safe)

__constant__ float c_invfact[NC] = {
    1.0f, 1.0f, 0.5f,
    1.6666666666666666e-01f, 4.1666666666666664e-02f, 8.3333333333333332e-03f,
    1.3888888888888889e-03f, 1.9841269841269841e-04f, 2.4801587301587302e-05f,
    2.7557319223985893e-06f, 2.7557319223985894e-07f, 2.5052108385441720e-08f,
    2.0876756987868100e-09f, 1.6059043836821616e-10f, 1.1470745597729726e-11f,
    7.6471637318198174e-13f };

// Exact fallback; never taken on this data. Shift m = |u|*kam >= max_j(u*k_j)
// is overflow-safe and cancels in the num/den ratio.
__device__ __noinline__ float exact_row(float u, const float* __restrict__ xb,
                                        const float* __restrict__ wkh,
                                        const float* __restrict__ wvh,
                                        float kam, float ki, float vi) {
    const float m = fabsf(u) * kam;
    float s1 = 0.f, s2 = 0.f;
    for (int j = 0; j < G_DIM; j++) {
        const float xj = xb[j];
        const float kj = xj * wkh[j];
        const float vj = xj * wvh[j];
        const float e  = __expf(fmaf(u, kj, -m));
        s1 += e;
        s2 = fmaf(e, vj, s2);
    }
    const float eii = __expf(fmaf(u, ki, -m));
    return (s2 - eii * vi) / s1;
}

// Shrinking butterfly round: N outputs from 2N inputs across stride S.
template<int S, int N>
__device__ __forceinline__ void red_round(const float* __restrict__ in,
                                          float* __restrict__ outv, int lane) {
    const bool up = (lane & S) != 0;
#pragma unroll
    for (int j = 0; j < N; j++) {
        const float send = up ? in[j] : in[j + N];
        const float recv = __shfl_xor_sync(0xffffffffu, send, S);
        outv[j] = (up ? in[j + N] : in[j]) + recv;
    }
}

// CTA (b,h). Phase A: moments for head h -> 32 coefficients + kam published to
// L2 (33 floats; cheap fence). Phase B: after all 5 CTAs of b published (spin
// ~ one L2 read; CTAs run in lockstep), evaluate rows [h*342,(h+1)*342) for
// ALL 5 heads and write out with plain coalesced stores. Single graph node:
// no memset, no atomics on out.
__global__ __launch_bounds__(NTHREADS, 1)
void attn_exchange_kernel(const float* __restrict__ x,  const float* __restrict__ WQ,
                          const float* __restrict__ WK, const float* __restrict__ WV,
                          const float* __restrict__ W0, float* __restrict__ out) {
    const int b = blockIdx.x;
    const int h = blockIdx.y;
    const int tid = threadIdx.x;
    const int wid = tid >> 5, lane = tid & 31;
    const bool act = (tid < GV4);

    __shared__ float wR[NWARPS][32];        // per-warp reduced (S0..15, M0..15)
    __shared__ float wkam[NWARPS];
    __shared__ float sc[H_DIM * 32];        // all 5 heads' coefficients
    __shared__ float skam[H_DIM];
    __shared__ unsigned s_target;

    const float4* __restrict__ xb4 = (const float4*)(x  + b * G_DIM);
    const float4* __restrict__ wk4 = (const float4*)(WK + h * G_DIM);
    const float4* __restrict__ wv4 = (const float4*)(WV + h * G_DIM);

    // ======== PHASE A: moments for (b,h) ========
    float4 xv = make_float4(0.f, 0.f, 0.f, 0.f), kw = xv, vw = xv;
    if (act) {
        xv = xb4[tid];
        kw = wk4[tid];
        vw = wv4[tid];
    }
    const float k0 = xv.x * kw.x, v0 = xv.x * vw.x;
    const float k1 = xv.y * kw.y, v1 = xv.y * vw.y;
    const float k2 = xv.z * kw.z, v2 = xv.z * vw.z;
    const float k3 = xv.w * kw.w, v3 = xv.w * vw.w;

    float kam = fmaxf(fmaxf(fabsf(k0), fabsf(k1)), fmaxf(fabsf(k2), fabsf(k3)));

    float R[32];
#pragma unroll
    for (int n = 0; n < 32; n++) R[n] = 0.f;
    if (act) {
#pragma unroll
        for (int e = 0; e < 4; e++) {
            const float k = (e == 0) ? k0 : (e == 1) ? k1 : (e == 2) ? k2 : k3;
            const float v = (e == 0) ? v0 : (e == 1) ? v1 : (e == 2) ? v2 : v3;
            const float ksq = k * k;
            const float kq  = ksq * ksq;
            float p0 = 1.f, p1 = k, p2 = ksq, p3 = ksq * k;
#pragma unroll
            for (int n = 0; n < NC; n += 4) {
                R[n + 0]      += p0;  R[NC + n + 0] = fmaf(p0, v, R[NC + n + 0]);
                R[n + 1]      += p1;  R[NC + n + 1] = fmaf(p1, v, R[NC + n + 1]);
                R[n + 2]      += p2;  R[NC + n + 2] = fmaf(p2, v, R[NC + n + 2]);
                R[n + 3]      += p3;  R[NC + n + 3] = fmaf(p3, v, R[NC + n + 3]);
                p0 *= kq; p1 *= kq; p2 *= kq; p3 *= kq;
            }
        }
    }

    // Shrinking-butterfly warp reduce: lane l ends with warp-sum of value l.
    float L16[16], L8[8], L4[4], L2[2], L1[1];
    red_round<16, 16>(R,   L16, lane);
    red_round< 8,  8>(L16, L8,  lane);
    red_round< 4,  4>(L8,  L4,  lane);
    red_round< 2,  2>(L4,  L2,  lane);
    red_round< 1,  1>(L2,  L1,  lane);
    wR[wid][lane] = L1[0];

#pragma unroll
    for (int o = 16; o > 0; o >>= 1)
        kam = fmaxf(kam, __shfl_xor_sync(0xffffffffu, kam, o));
    if (lane == 0) wkam[wid] = kam;
    __syncthreads();

    // Cross-warp finalize -> publish 33 floats to global (light release).
    if (tid < 32) {
        float s = 0.f;
#pragma unroll
        for (int w = 0; w < NWARPS; w++) s += wR[w][tid];
        const float inv = c_invfact[(tid < NC) ? tid : (tid - NC)];
        g_coef[(b * H_DIM + h) * 32 + tid] = s * inv;
        __threadfence();
    } else if (tid == 32) {
        float a = 0.f;
#pragma unroll
        for (int w = 0; w < NWARPS; w++) a = fmaxf(a, wkam[w]);
        g_kam[b * H_DIM + h] = a;
        __threadfence();
    }
    __syncthreads();                 // all publishing threads have fenced
    if (tid == 0) {
        const unsigned t = atomicAdd(&g_cnt[b], 1u);
        s_target = (t / H_DIM) * H_DIM + H_DIM;   // replay-safe epoch target
    }
    __syncthreads();

    // ======== PHASE B: wait (short; CTAs in lockstep), gather, evaluate ========
    if (tid == 0) {
        const unsigned target = s_target;
        volatile unsigned* vc = &g_cnt[b];
        while ((int)(*vc - target) < 0) { __nanosleep(32); }
    }
    __syncthreads();
    __threadfence();                 // acquire: peers' 33-float publishes visible

    if (tid < H_DIM * 32)      sc[tid]   = g_coef[b * H_DIM * 32 + tid];
    else if (tid < H_DIM * 33) skam[tid - H_DIM * 32] = g_kam[b * H_DIM + (tid - H_DIM * 32)];
    __syncthreads();

    // Evaluate rows [h*CHUNK, (h+1)*CHUNK) for all heads; plain store.
    const int r = h * CHUNK + tid;
    if (tid < CHUNK && r < G_DIM) {
        const float xi = x[b * G_DIM + r];
        float w0c[H_DIM];
#pragma unroll
        for (int hh = 0; hh < H_DIM; hh++) w0c[hh] = W0[hh];

        float acc = 0.f;
#pragma unroll
        for (int hh = 0; hh < H_DIM; hh++) {
            const float u  = xi * WQ[hh * G_DIM + r];
            const float ki = xi * WK[hh * G_DIM + r];
            const float vi = xi * WV[hh * G_DIM + r];
            const float kamh = skam[hh];
            const float* ch = sc + hh * 32;
            float o;
            if (fabsf(u) * kamh <= GUARD) {
                float den = ch[NC - 1];
                float num = ch[2 * NC - 1];
#pragma unroll
                for (int n = NC - 2; n >= 0; n--) {
                    den = fmaf(den, u, ch[n]);
                    num = fmaf(num, u, ch[NC + n]);
                }
                const float eii = __expf(u * ki);   // diagonal, masked post-softmax
                o = __fdividef(num - eii * vi, den);
            } else {
                o = exact_row(u, x + b * G_DIM, WK + hh * G_DIM, WV + hh * G_DIM,
                              kamh, ki, vi);
            }
            acc = fmaf(w0c[hh], o, acc);
        }
        out[b * G_DIM + r] = acc;
    }
}

extern "C" void kernel_launch(void* const* d_in, const int* in_sizes, int n_in,
                              void* d_out, int out_size) {
    const float* x  = (const float*)d_in[0];
    const float* WQ = (const float*)d_in[1];
    const float* WK = (const float*)d_in[2];
    const float* WV = (const float*)d_in[3];
    const float* W0 = (const float*)d_in[4];
    float* out = (float*)d_out;

    dim3 grid(B_DIM, H_DIM);
    attn_exchange_kernel<<<grid, NTHREADS>>>(x, WQ, WK, WV, W0, out);
}

// round 17
// speedup vs baseline: 1.2308x; 1.2308x over previous
#include <cuda_runtime.h>

#define B_DIM 16
#define G_DIM 1708
#define GV4   (G_DIM / 4)        // 427 active float4 groups in phase A
#define H_DIM 5
#define NC 16                    // Taylor n = 0..15; 4.5^16/16!/e^4.5 ~ 1.5e-5 at guard
#define GUARD 4.5f
#define NTHREADS 448
#define NWARPS 14
#define CHUNK ((G_DIM + H_DIM - 1) / H_DIM)   // 342 rows per CTA in phase B

// Per-(b,h) coefficients [S0..15, M0..15] (already /n!) + kam; tiny L2 exchange.
__device__ float    g_coef[B_DIM * H_DIM * 32];
__device__ float    g_kam[B_DIM * H_DIM];
__device__ unsigned g_cnt[B_DIM];   // monotone publish counter (replay-safe)

__constant__ float c_invfact[NC] = {
    1.0f, 1.0f, 0.5f,
    1.6666666666666666e-01f, 4.1666666666666664e-02f, 8.3333333333333332e-03f,
    1.3888888888888889e-03f, 1.9841269841269841e-04f, 2.4801587301587302e-05f,
    2.7557319223985893e-06f, 2.7557319223985894e-07f, 2.5052108385441720e-08f,
    2.0876756987868100e-09f, 1.6059043836821616e-10f, 1.1470745597729726e-11f,
    7.6471637318198174e-13f };

// Exact fallback; never taken on this data. Shift m = |u|*kam >= max_j(u*k_j)
// is overflow-safe and cancels in the num/den ratio.
__device__ __noinline__ float exact_row(float u, const float* __restrict__ xb,
                                        const float* __restrict__ wkh,
                                        const float* __restrict__ wvh,
                                        float kam, float ki, float vi) {
    const float m = fabsf(u) * kam;
    float s1 = 0.f, s2 = 0.f;
    for (int j = 0; j < G_DIM; j++) {
        const float xj = xb[j];
        const float kj = xj * wkh[j];
        const float vj = xj * wvh[j];
        const float e  = __expf(fmaf(u, kj, -m));
        s1 += e;
        s2 = fmaf(e, vj, s2);
    }
    const float eii = __expf(fmaf(u, ki, -m));
    return (s2 - eii * vi) / s1;
}

// Shrinking butterfly round: N outputs from 2N inputs across stride S.
template<int S, int N>
__device__ __forceinline__ void red_round(const float* __restrict__ in,
                                          float* __restrict__ outv, int lane) {
    const bool up = (lane & S) != 0;
#pragma unroll
    for (int j = 0; j < N; j++) {
        const float send = up ? in[j] : in[j + N];
        const float recv = __shfl_xor_sync(0xffffffffu, send, S);
        outv[j] = (up ? in[j + N] : in[j]) + recv;
    }
}

// CTA (b,h). Entry: prefetch EVERYTHING (phase-A float4 group + phase-B row
// scalars for all 5 heads) in one MLP batch. Phase A: moments for head h ->
// 33 floats published to L2 (cheap fence). Phase B: after all 5 CTAs of b
// published (short spin), evaluate rows [h*342,(h+1)*342) for ALL heads from
// registers + smem coefficients; plain coalesced store. Single graph node.
__global__ __launch_bounds__(NTHREADS, 1)
void attn_exchange_kernel(const float* __restrict__ x,  const float* __restrict__ WQ,
                          const float* __restrict__ WK, const float* __restrict__ WV,
                          const float* __restrict__ W0, float* __restrict__ out) {
    const int b = blockIdx.x;
    const int h = blockIdx.y;
    const int tid = threadIdx.x;
    const int wid = tid >> 5, lane = tid & 31;
    const bool act  = (tid < GV4);
    const int  r    = h * CHUNK + tid;                 // phase-B row this thread owns
    const bool actB = (tid < CHUNK) && (r < G_DIM);

    __shared__ float wR[NWARPS][32];        // per-warp reduced (S0..15, M0..15)
    __shared__ float wkam[NWARPS];
    __shared__ float sc[H_DIM * 32];        // all 5 heads' coefficients
    __shared__ float skam[H_DIM];
    __shared__ unsigned s_target;

    const float4* __restrict__ xb4 = (const float4*)(x  + b * G_DIM);
    const float4* __restrict__ wk4 = (const float4*)(WK + h * G_DIM);
    const float4* __restrict__ wv4 = (const float4*)(WV + h * G_DIM);

    // ======== Prefetch: ALL loads issued here, one DRAM round-trip ========
    float4 xv = make_float4(0.f, 0.f, 0.f, 0.f), kw = xv, vw = xv;
    if (act) {
        xv = xb4[tid];
        kw = wk4[tid];
        vw = wv4[tid];
    }
    // Phase-B row data: x_r and per-head WQ/WK/WV at row r (latency hidden
    // under phase A + reduction + spin).
    float xr = 0.f, qr[H_DIM], kr[H_DIM], vr[H_DIM], w0c[H_DIM];
#pragma unroll
    for (int hh = 0; hh < H_DIM; hh++) { qr[hh] = 0.f; kr[hh] = 0.f; vr[hh] = 0.f; }
    if (actB) {
        xr = x[b * G_DIM + r];
#pragma unroll
        for (int hh = 0; hh < H_DIM; hh++) {
            qr[hh] = WQ[hh * G_DIM + r];
            kr[hh] = WK[hh * G_DIM + r];
            vr[hh] = WV[hh * G_DIM + r];
        }
    }
#pragma unroll
    for (int hh = 0; hh < H_DIM; hh++) w0c[hh] = W0[hh];

    // ======== PHASE A: moments for (b,h) ========
    const float k0 = xv.x * kw.x, v0 = xv.x * vw.x;
    const float k1 = xv.y * kw.y, v1 = xv.y * vw.y;
    const float k2 = xv.z * kw.z, v2 = xv.z * vw.z;
    const float k3 = xv.w * kw.w, v3 = xv.w * vw.w;

    float kam = fmaxf(fmaxf(fabsf(k0), fabsf(k1)), fmaxf(fabsf(k2), fabsf(k3)));

    float R[32];
#pragma unroll
    for (int n = 0; n < 32; n++) R[n] = 0.f;
    if (act) {
#pragma unroll
        for (int e = 0; e < 4; e++) {
            const float k = (e == 0) ? k0 : (e == 1) ? k1 : (e == 2) ? k2 : k3;
            const float v = (e == 0) ? v0 : (e == 1) ? v1 : (e == 2) ? v2 : v3;
            const float ksq = k * k;
            const float kq  = ksq * ksq;
            float p0 = 1.f, p1 = k, p2 = ksq, p3 = ksq * k;
#pragma unroll
            for (int n = 0; n < NC; n += 4) {
                R[n + 0]      += p0;  R[NC + n + 0] = fmaf(p0, v, R[NC + n + 0]);
                R[n + 1]      += p1;  R[NC + n + 1] = fmaf(p1, v, R[NC + n + 1]);
                R[n + 2]      += p2;  R[NC + n + 2] = fmaf(p2, v, R[NC + n + 2]);
                R[n + 3]      += p3;  R[NC + n + 3] = fmaf(p3, v, R[NC + n + 3]);
                p0 *= kq; p1 *= kq; p2 *= kq; p3 *= kq;
            }
        }
    }

    // Shrinking-butterfly warp reduce: lane l ends with warp-sum of value l.
    float L16[16], L8[8], L4[4], L2[2], L1[1];
    red_round<16, 16>(R,   L16, lane);
    red_round< 8,  8>(L16, L8,  lane);
    red_round< 4,  4>(L8,  L4,  lane);
    red_round< 2,  2>(L4,  L2,  lane);
    red_round< 1,  1>(L2,  L1,  lane);
    wR[wid][lane] = L1[0];

#pragma unroll
    for (int o = 16; o > 0; o >>= 1)
        kam = fmaxf(kam, __shfl_xor_sync(0xffffffffu, kam, o));
    if (lane == 0) wkam[wid] = kam;
    __syncthreads();

    // Cross-warp finalize -> publish 33 floats to global (light release).
    if (tid < 32) {
        float s = 0.f;
#pragma unroll
        for (int w = 0; w < NWARPS; w++) s += wR[w][tid];
        const float inv = c_invfact[(tid < NC) ? tid : (tid - NC)];
        g_coef[(b * H_DIM + h) * 32 + tid] = s * inv;
        __threadfence();
    } else if (tid == 32) {
        float a = 0.f;
#pragma unroll
        for (int w = 0; w < NWARPS; w++) a = fmaxf(a, wkam[w]);
        g_kam[b * H_DIM + h] = a;
        __threadfence();
    }
    __syncthreads();                 // all publishing threads have fenced
    if (tid == 0) {
        const unsigned t = atomicAdd(&g_cnt[b], 1u);
        s_target = (t / H_DIM) * H_DIM + H_DIM;   // replay-safe epoch target
    }
    __syncthreads();

    // ======== PHASE B: short wait, gather coefficients, evaluate ========
    if (tid == 0) {
        const unsigned target = s_target;
        volatile unsigned* vc = &g_cnt[b];
        while ((int)(*vc - target) < 0) { __nanosleep(32); }
    }
    __syncthreads();
    __threadfence();                 // acquire: peers' 33-float publishes visible

    if (tid < H_DIM * 32)      sc[tid] = g_coef[b * H_DIM * 32 + tid];
    else if (tid < H_DIM * 33) skam[tid - H_DIM * 32] = g_kam[b * H_DIM + (tid - H_DIM * 32)];
    __syncthreads();

    // Evaluate this CTA's row slice for all heads; everything in registers/smem.
    if (actB) {
        float acc = 0.f;
#pragma unroll
        for (int hh = 0; hh < H_DIM; hh++) {
            const float u  = xr * qr[hh];
            const float ki = xr * kr[hh];
            const float vi = xr * vr[hh];
            const float kamh = skam[hh];
            const float* ch = sc + hh * 32;
            float o;
            if (fabsf(u) * kamh <= GUARD) {
                float den = ch[NC - 1];
                float num = ch[2 * NC - 1];
#pragma unroll
                for (int n = NC - 2; n >= 0; n--) {
                    den = fmaf(den, u, ch[n]);
                    num = fmaf(num, u, ch[NC + n]);
                }
                const float eii = __expf(u * ki);   // diagonal, masked post-softmax
                o = __fdividef(num - eii * vi, den);
            } else {
                o = exact_row(u, x + b * G_DIM, WK + hh * G_DIM, WV + hh * G_DIM,
                              kamh, ki, vi);
            }
            acc = fmaf(w0c[hh], o, acc);
        }
        out[b * G_DIM + r] = acc;
    }
}

extern "C" void kernel_launch(void* const* d_in, const int* in_sizes, int n_in,
                              void* d_out, int out_size) {
    const float* x  = (const float*)d_in[0];
    const float* WQ = (const float*)d_in[1];
    const float* WK = (const float*)d_in[2];
    const float* WV = (const float*)d_in[3];
    const float* W0 = (const float*)d_in[4];
    float* out = (float*)d_out;

    dim3 grid(B_DIM, H_DIM);
    attn_exchange_kernel<<<grid, NTHREADS>>>(x, WQ, WK, WV, W0, out);
}